// round 8
// baseline (speedup 1.0000x reference)
#include <cuda_runtime.h>
#include <cuda_bf16.h>

#define BB 2048
#define TT 128
#define NN 64
#define HH 128
#define THR 512   // threads per CTA (16 warps)
#define NFULL 124 // CTAs with 14 batches; rest have 13
#define HCP 264   // padded hc row stride (floats)
#define SUP 132   // padded sU row stride (floats)

typedef unsigned long long ull;

// ---------------- device scratch (allocation-free: __device__ globals) -------
__device__ __align__(16) __nv_bfloat16 g_prex_bf[(size_t)BB * NN * HH]; // [b][n][k]
__device__ __align__(16) float g_WhsT[256 * HH];   // [j][k] fp32 attention weights
__device__ __align__(16) float g_W1xT[TT * HH];    // [t][k]
__device__ __align__(16) uint2 g_WhhB[HH * 128];   // [j][q] bf16x2 pair {(i,f),(g,o)}
__device__ __align__(16) uint2 g_WihB[NN * 128];   // [n][q]
__device__ __align__(16) float g_bG[512];          // [q*4+gate]

__device__ __forceinline__ ull pk2(float a, float b) {
    ull r; asm("mov.b64 %0,{%1,%2};" : "=l"(r) : "f"(a), "f"(b)); return r;
}
__device__ __forceinline__ void fma2(ull& d, ull a, ull b) {
    asm("fma.rn.f32x2 %0, %1, %2, %0;" : "+l"(d) : "l"(a), "l"(b));
}
__device__ __forceinline__ float2 up2(ull v) {
    float2 r; asm("mov.b64 {%0,%1},%2;" : "=f"(r.x), "=f"(r.y) : "l"(v)); return r;
}
// bf16x2 word -> packed f32x2 (low bf16 -> low f32)
__device__ __forceinline__ ull expw(unsigned wd) {
    unsigned lo = wd << 16, hi = wd & 0xFFFF0000u;
    ull r; asm("mov.b64 %0,{%1,%2};" : "=l"(r) : "r"(lo), "r"(hi)); return r;
}
__device__ __forceinline__ float tanh_fast(float x) {
    float y; asm("tanh.approx.f32 %0, %1;" : "=f"(y) : "f"(x)); return y;
}
__device__ __forceinline__ float sigmoid_f(float x) {
    return 1.0f / (1.0f + __expf(-x));
}
__device__ __forceinline__ void fma4(float4& a, float s, const float4 w) {
    a.x = fmaf(s, w.x, a.x); a.y = fmaf(s, w.y, a.y);
    a.z = fmaf(s, w.z, a.z); a.w = fmaf(s, w.w, a.w);
}
__device__ __forceinline__ unsigned b2u(__nv_bfloat162 v) {
    unsigned r; *(__nv_bfloat162*)&r = v; return r;
}

// ---------------- kernel 0: weight layout prep --------------------------------
__global__ void prep_kernel(const float* __restrict__ W_attn1,
                            const float* __restrict__ W_ih,
                            const float* __restrict__ W_hh,
                            const float* __restrict__ b_ih,
                            const float* __restrict__ b_hh)
{
    int tid = blockIdx.x * blockDim.x + threadIdx.x;
    int nt  = gridDim.x * blockDim.x;
    for (int i = tid; i < 256 * HH; i += nt) {
        int j = i >> 7, k = i & 127;
        g_WhsT[i] = W_attn1[k * 384 + j];
    }
    for (int i = tid; i < TT * HH; i += nt) {
        int t = i >> 7, k = i & 127;
        g_W1xT[i] = W_attn1[k * 384 + 256 + t];
    }
    for (int i = tid; i < HH * 128; i += nt) {
        int j = i >> 7, q = i & 127;
        uint2 v;
        v.x = b2u(__floats2bfloat162_rn(W_hh[(0*HH+q)*HH + j], W_hh[(1*HH+q)*HH + j]));
        v.y = b2u(__floats2bfloat162_rn(W_hh[(2*HH+q)*HH + j], W_hh[(3*HH+q)*HH + j]));
        g_WhhB[i] = v;
    }
    for (int i = tid; i < NN * 128; i += nt) {
        int n = i >> 7, q = i & 127;
        uint2 v;
        v.x = b2u(__floats2bfloat162_rn(W_ih[(0*HH+q)*NN + n], W_ih[(1*HH+q)*NN + n]));
        v.y = b2u(__floats2bfloat162_rn(W_ih[(2*HH+q)*NN + n], W_ih[(3*HH+q)*NN + n]));
        g_WihB[i] = v;
    }
    for (int i = tid; i < 512; i += nt) {
        int q = i >> 2, g = i & 3;
        g_bG[i] = b_ih[g * HH + q] + b_hh[g * HH + q];
    }
}

// ---------------- kernel 1: pre_x (bf16 out) ----------------------------------
__global__ __launch_bounds__(256) void prex_kernel(const float* __restrict__ X,
                                                   const float* __restrict__ b_attn1)
{
    __shared__ float sX[TT * NN];
    int b = blockIdx.x;
    int tid = threadIdx.x;
    const float* Xb = X + (size_t)b * TT * NN;
    for (int i = tid; i < TT * NN; i += 256) sX[i] = Xb[i];
    __syncthreads();

    const float4* W4  = (const float4*)g_W1xT;
    const float4* b14 = (const float4*)b_attn1;
    uint2* out2 = (uint2*)(g_prex_bf + (size_t)b * NN * HH);

    for (int qi = tid; qi < NN * 32; qi += 256) {
        int n = qi >> 5, kq = qi & 31;
        float4 acc = b14[kq];
        #pragma unroll 4
        for (int t = 0; t < TT; ++t) {
            float x = sX[t * NN + n];
            fma4(acc, x, W4[t * 32 + kq]);
        }
        uint2 st;
        st.x = b2u(__floats2bfloat162_rn(acc.x, acc.y));
        st.y = b2u(__floats2bfloat162_rn(acc.z, acc.w));
        out2[n * 32 + kq] = st;
    }
}

// dummy: shifts launch numbering so ncu (-s 5 -c 1) lands on rnn_kernel
__global__ void dummy_kernel() {}

// ---------------- kernel 2: the recurrence ------------------------------------
// smem (floats): sW 32768 | hcA 4224 | hcB 4224 | sU 2112 | sXT 1024
#define SMEM_FLOATS (32768 + 4224 + 4224 + 2112 + 1024)

#define PKS(c) p0 = pk2(v0.c, v0.c); p1 = pk2(v1.c, v1.c); \
               p2 = pk2(v2.c, v2.c); p3 = pk2(v3.c, v3.c)
#define GSTEP(wl, wh) { ull wx = expw(wl), wy = expw(wh); \
    fma2(aL0, p0, wx); fma2(aH0, p0, wy); fma2(aL1, p1, wx); fma2(aH1, p1, wy); \
    fma2(aL2, p2, wx); fma2(aH2, p2, wy); fma2(aL3, p3, wx); fma2(aH3, p3, wy); }

__global__ __launch_bounds__(THR, 1) void rnn_kernel(
    const float* __restrict__ X,
    const float* __restrict__ w_attn2,
    const float* __restrict__ b_attn2,
    float* __restrict__ out)
{
    extern __shared__ float smem[];
    float* sW  = smem;
    float* hcA = sW + 32768;
    float* hcB = hcA + 4224;
    float* sU  = hcB + 4224;
    float* sXT = sU + 2112;

    int tid = threadIdx.x;
    int l = tid & 31;
    int w = tid >> 5;
    int cta = blockIdx.x;
    int cnt  = (cta < NFULL) ? 14 : 13;
    size_t b0 = (cta < NFULL) ? (size_t)cta * 14
                              : (size_t)(NFULL * 14 + (cta - NFULL) * 13);

    {   // stage attention weights fp32 into smem (once)
        const float4* src = (const float4*)g_WhsT;
        float4* dst = (float4*)sW;
        #pragma unroll 4
        for (int i = tid; i < 8192; i += THR) dst[i] = src[i];
    }
    for (int i = tid; i < 8448; i += THR) hcA[i] = 0.0f;
    for (int i = tid; i < 1024; i += THR) sXT[i] = 0.0f;

    float b2 = b_attn2[0];

    // (a) mapping
    int mA  = (w >> 2) * 4 + (l >> 3);
    int kqA = (w & 3) * 8 + (l & 7);

    // (d) mapping
    int q = tid & 127, grp = tid >> 7, mb = grp * 4;
    float4 bgq = ((const float4*)g_bG)[q];
    ull bLo = pk2(bgq.x, bgq.y), bHi = pk2(bgq.z, bgq.w);

    int mw = (w < cnt) ? w : 0;
    const uint2* prb = (const uint2*)g_prex_bf + (size_t)(b0 + mw) * 2048;

    __syncthreads();

    for (int t = 0; t < TT; ++t) {
        float* hc  = (t & 1) ? hcB : hcA;
        float* hcn = (t & 1) ? hcA : hcB;

        // ---- (a) u[m][k] = sum_j [h|c][m][j] * WhsT[j][k]  (smem fp32)
        {
            const float4* hcm4 = (const float4*)(hc + mA * HCP);
            const ulonglong2* sW2 = (const ulonglong2*)sW;   // [j][32]
            ull a0 = 0ull, a1 = 0ull;
            #pragma unroll 4
            for (int j4 = 0; j4 < 64; ++j4) {
                float4 hv = hcm4[j4];
                ulonglong2 w0 = sW2[(j4 * 4 + 0) * 32 + kqA];
                ulonglong2 w1 = sW2[(j4 * 4 + 1) * 32 + kqA];
                ulonglong2 w2 = sW2[(j4 * 4 + 2) * 32 + kqA];
                ulonglong2 w3 = sW2[(j4 * 4 + 3) * 32 + kqA];
                ull p0 = pk2(hv.x, hv.x), p1 = pk2(hv.y, hv.y);
                ull p2 = pk2(hv.z, hv.z), p3 = pk2(hv.w, hv.w);
                fma2(a0, p0, w0.x); fma2(a1, p0, w0.y);
                fma2(a0, p1, w1.x); fma2(a1, p1, w1.y);
                fma2(a0, p2, w2.x); fma2(a1, p2, w2.y);
                fma2(a0, p3, w3.x); fma2(a1, p3, w3.y);
            }
            float2 r0 = up2(a0), r1 = up2(a1);
            ((float4*)(sU + mA * SUP))[kqA] = make_float4(r0.x, r0.y, r1.x, r1.y);
        }
        __syncthreads();

        // ---- (b)+(c): e, softmax, x_tilde. warp=m; lane ends with e[n=l].
        if (w < cnt) {
            int kq = l & 7;
            const float4* sUr = (const float4*)(sU + w * SUP);
            float4 u0 = sUr[kq], u1 = sUr[kq + 8], u2 = sUr[kq + 16], u3 = sUr[kq + 24];
            const float4* w24 = (const float4*)w_attn2;
            float4 wA = w24[kq], wB = w24[kq + 8], wC = w24[kq + 16], wD = w24[kq + 24];
            float ee[2];
            #pragma unroll
            for (int p = 0; p < 2; ++p) {
                int nb = p * 32 + (l & 24);
                const uint2* pp = prb + (size_t)nb * 32 + kq;
                uint2 c0 = __ldcs(pp), c1 = __ldcs(pp + 8);
                uint2 c2 = __ldcs(pp + 16), c3 = __ldcs(pp + 24);
                float v[8];
                #pragma unroll
                for (int i = 0; i < 8; ++i) {
                    const uint2* pn = prb + (size_t)(nb + ((i + 1) & 7)) * 32 + kq;
                    uint2 n0 = __ldcs(pn), n1 = __ldcs(pn + 8);
                    uint2 n2 = __ldcs(pn + 16), n3 = __ldcs(pn + 24);
                    float s;
                    {
                        float2 a01 = __bfloat1622float2(*(const __nv_bfloat162*)&c0.x);
                        float2 a23 = __bfloat1622float2(*(const __nv_bfloat162*)&c0.y);
                        s = tanh_fast(a01.x + u0.x) * wA.x;
                        s = fmaf(tanh_fast(a01.y + u0.y), wA.y, s);
                        s = fmaf(tanh_fast(a23.x + u0.z), wA.z, s);
                        s = fmaf(tanh_fast(a23.y + u0.w), wA.w, s);
                    }
                    {
                        float2 a01 = __bfloat1622float2(*(const __nv_bfloat162*)&c1.x);
                        float2 a23 = __bfloat1622float2(*(const __nv_bfloat162*)&c1.y);
                        s = fmaf(tanh_fast(a01.x + u1.x), wB.x, s);
                        s = fmaf(tanh_fast(a01.y + u1.y), wB.y, s);
                        s = fmaf(tanh_fast(a23.x + u1.z), wB.z, s);
                        s = fmaf(tanh_fast(a23.y + u1.w), wB.w, s);
                    }
                    {
                        float2 a01 = __bfloat1622float2(*(const __nv_bfloat162*)&c2.x);
                        float2 a23 = __bfloat1622float2(*(const __nv_bfloat162*)&c2.y);
                        s = fmaf(tanh_fast(a01.x + u2.x), wC.x, s);
                        s = fmaf(tanh_fast(a01.y + u2.y), wC.y, s);
                        s = fmaf(tanh_fast(a23.x + u2.z), wC.z, s);
                        s = fmaf(tanh_fast(a23.y + u2.w), wC.w, s);
                    }
                    {
                        float2 a01 = __bfloat1622float2(*(const __nv_bfloat162*)&c3.x);
                        float2 a23 = __bfloat1622float2(*(const __nv_bfloat162*)&c3.y);
                        s = fmaf(tanh_fast(a01.x + u3.x), wD.x, s);
                        s = fmaf(tanh_fast(a01.y + u3.y), wD.y, s);
                        s = fmaf(tanh_fast(a23.x + u3.z), wD.z, s);
                        s = fmaf(tanh_fast(a23.y + u3.w), wD.w, s);
                    }
                    v[i] = s;
                    c0 = n0; c1 = n1; c2 = n2; c3 = n3;
                }
                bool h1 = l & 1, h2 = l & 2, h4 = l & 4;
                float s0 = h1 ? v[0] : v[1];
                float a0 = (h1 ? v[1] : v[0]) + __shfl_xor_sync(0xffffffffu, s0, 1);
                float s1 = h1 ? v[2] : v[3];
                float a1 = (h1 ? v[3] : v[2]) + __shfl_xor_sync(0xffffffffu, s1, 1);
                float s2 = h1 ? v[4] : v[5];
                float a2 = (h1 ? v[5] : v[4]) + __shfl_xor_sync(0xffffffffu, s2, 1);
                float s3 = h1 ? v[6] : v[7];
                float a3 = (h1 ? v[7] : v[6]) + __shfl_xor_sync(0xffffffffu, s3, 1);
                float t0 = h2 ? a0 : a1;
                float bb0 = (h2 ? a1 : a0) + __shfl_xor_sync(0xffffffffu, t0, 2);
                float t1 = h2 ? a2 : a3;
                float bb1 = (h2 ? a3 : a2) + __shfl_xor_sync(0xffffffffu, t1, 2);
                float t2 = h4 ? bb0 : bb1;
                float ev = (h4 ? bb1 : bb0) + __shfl_xor_sync(0xffffffffu, t2, 4);
                ee[p] = ev + b2;
            }
            float e0 = ee[0], e1 = ee[1];
            float mx = fmaxf(e0, e1);
            #pragma unroll
            for (int o = 16; o > 0; o >>= 1)
                mx = fmaxf(mx, __shfl_xor_sync(0xffffffffu, mx, o));
            float x0 = __expf(e0 - mx), x1 = __expf(e1 - mx);
            float sm = x0 + x1;
            #pragma unroll
            for (int o = 16; o > 0; o >>= 1)
                sm += __shfl_xor_sync(0xffffffffu, sm, o);
            float inv = 1.0f / sm;
            const float* Xr = X + ((size_t)(b0 + w) * TT + t) * NN;
            sXT[w * 64 + l]      = x0 * inv * Xr[l];
            sXT[w * 64 + l + 32] = x1 * inv * Xr[l + 32];
        }
        __syncthreads();

        // ---- (d) gates for batches mb..mb+3 at gate-quad q (bf16 wts, f32x2 acc)
        ull aL0 = bLo, aH0 = bHi, aL1 = bLo, aH1 = bHi;
        ull aL2 = bLo, aH2 = bHi, aL3 = bLo, aH3 = bHi;
        {
            const float4* h40 = (const float4*)(hc + (mb + 0) * HCP);
            const float4* h41 = (const float4*)(hc + (mb + 1) * HCP);
            const float4* h42 = (const float4*)(hc + (mb + 2) * HCP);
            const float4* h43 = (const float4*)(hc + (mb + 3) * HCP);
            const uint2* Wh = g_WhhB + q;
            uint2 wq0 = Wh[0], wq1 = Wh[128], wq2 = Wh[256], wq3 = Wh[384];
            #pragma unroll 4
            for (int j4 = 0; j4 < 32; ++j4) {
                int nj = ((j4 + 1) & 31) * 4;
                uint2 f0 = Wh[(size_t)(nj + 0) * 128];
                uint2 f1 = Wh[(size_t)(nj + 1) * 128];
                uint2 f2 = Wh[(size_t)(nj + 2) * 128];
                uint2 f3 = Wh[(size_t)(nj + 3) * 128];
                float4 v0 = h40[j4], v1 = h41[j4], v2 = h42[j4], v3 = h43[j4];
                ull p0, p1, p2, p3;
                PKS(x); GSTEP(wq0.x, wq0.y);
                PKS(y); GSTEP(wq1.x, wq1.y);
                PKS(z); GSTEP(wq2.x, wq2.y);
                PKS(w); GSTEP(wq3.x, wq3.y);
                wq0 = f0; wq1 = f1; wq2 = f2; wq3 = f3;
            }
            const float4* x40 = (const float4*)(sXT + (mb + 0) * 64);
            const float4* x41 = (const float4*)(sXT + (mb + 1) * 64);
            const float4* x42 = (const float4*)(sXT + (mb + 2) * 64);
            const float4* x43 = (const float4*)(sXT + (mb + 3) * 64);
            const uint2* Wi = g_WihB + q;
            wq0 = Wi[0]; wq1 = Wi[128]; wq2 = Wi[256]; wq3 = Wi[384];
            #pragma unroll 4
            for (int n4 = 0; n4 < 16; ++n4) {
                int nj = ((n4 + 1) & 15) * 4;
                uint2 f0 = Wi[(size_t)(nj + 0) * 128];
                uint2 f1 = Wi[(size_t)(nj + 1) * 128];
                uint2 f2 = Wi[(size_t)(nj + 2) * 128];
                uint2 f3 = Wi[(size_t)(nj + 3) * 128];
                float4 v0 = x40[n4], v1 = x41[n4], v2 = x42[n4], v3 = x43[n4];
                ull p0, p1, p2, p3;
                PKS(x); GSTEP(wq0.x, wq0.y);
                PKS(y); GSTEP(wq1.x, wq1.y);
                PKS(z); GSTEP(wq2.x, wq2.y);
                PKS(w); GSTEP(wq3.x, wq3.y);
                wq0 = f0; wq1 = f1; wq2 = f2; wq3 = f3;
            }
        }

        // ---- (e) LSTM pointwise update -> double-buffered state + output
        #pragma unroll
        for (int mm = 0; mm < 4; ++mm) {
            if (mb + mm < cnt) {
                ull aL = (mm == 0) ? aL0 : (mm == 1) ? aL1 : (mm == 2) ? aL2 : aL3;
                ull aH = (mm == 0) ? aH0 : (mm == 1) ? aH1 : (mm == 2) ? aH2 : aH3;
                float2 gif = up2(aL);
                float2 ggo = up2(aH);
                float iv = sigmoid_f(gif.x);
                float fv = sigmoid_f(gif.y);
                float gv = tanhf(ggo.x);
                float ov = sigmoid_f(ggo.y);
                float cold = hc[(mb + mm) * HCP + 128 + q];
                float c2 = fv * cold + iv * gv;
                float hn = ov * tanhf(c2);
                hcn[(mb + mm) * HCP + q]       = hn;
                hcn[(mb + mm) * HCP + 128 + q] = c2;
                out[((size_t)(b0 + mb + mm) * TT + t) * HH + q] = hn;
            }
        }
        __syncthreads();
    }
}

// ---------------- launch ------------------------------------------------------
extern "C" void kernel_launch(void* const* d_in, const int* in_sizes, int n_in,
                              void* d_out, int out_size) {
    const float* X       = (const float*)d_in[0];
    const float* W_attn1 = (const float*)d_in[1];
    const float* b_attn1 = (const float*)d_in[2];
    const float* w_attn2 = (const float*)d_in[3];
    const float* b_attn2 = (const float*)d_in[4];
    const float* W_ih    = (const float*)d_in[5];
    const float* W_hh    = (const float*)d_in[6];
    const float* b_ih    = (const float*)d_in[7];
    const float* b_hh    = (const float*)d_in[8];
    float* out = (float*)d_out;

    cudaFuncSetAttribute(rnn_kernel, cudaFuncAttributeMaxDynamicSharedMemorySize,
                         SMEM_FLOATS * (int)sizeof(float));

    prep_kernel<<<64, 256>>>(W_attn1, W_ih, W_hh, b_ih, b_hh);
    prex_kernel<<<BB, 256>>>(X, b_attn1);
    dummy_kernel<<<1, 32>>>();   // aligns ncu -s 5 -c 1 onto rnn_kernel
    rnn_kernel<<<148, THR, SMEM_FLOATS * sizeof(float)>>>(X, w_attn2, b_attn2, out);
}

// round 9
// speedup vs baseline: 1.1824x; 1.1824x over previous
#include <cuda_runtime.h>
#include <cuda_bf16.h>

#define BB 2048
#define TT 128
#define NN 64
#define HH 128
#define THR 256   // threads per CTA (8 warps)
#define NFULL 272 // CTAs with 7 batches; rest have 6 (272*7 + 24*6 = 2048)
#define GRID 296  // 2 CTAs per SM
#define HCP 264   // padded hc row stride (floats)
#define SUP 132   // padded sU row stride (floats)

typedef unsigned long long ull;

// ---------------- device scratch (allocation-free: __device__ globals) -------
__device__ __align__(16) __nv_bfloat16 g_prex_bf[(size_t)BB * NN * HH]; // [b][n][k]
__device__ __align__(16) uint2 g_WhsB[256 * 32];   // [j][kq] bf16x4 attention wts
__device__ __align__(16) float g_W1xT[TT * HH];    // [t][k]
__device__ __align__(16) float g_WihG[NN * 512];   // [n][q*4+gate] fp32
__device__ __align__(16) float g_WhhG[HH * 512];   // [j][q*4+gate] fp32
__device__ __align__(16) float g_bG[512];          // [q*4+gate]

__device__ __forceinline__ ull pk2(float a, float b) {
    ull r; asm("mov.b64 %0,{%1,%2};" : "=l"(r) : "f"(a), "f"(b)); return r;
}
__device__ __forceinline__ void fma2(ull& d, ull a, ull b) {
    asm("fma.rn.f32x2 %0, %1, %2, %0;" : "+l"(d) : "l"(a), "l"(b));
}
__device__ __forceinline__ float2 up2(ull v) {
    float2 r; asm("mov.b64 {%0,%1},%2;" : "=f"(r.x), "=f"(r.y) : "l"(v)); return r;
}
// bf16x2 word -> packed f32x2 (low bf16 -> low f32)
__device__ __forceinline__ ull expw(unsigned wd) {
    unsigned lo = wd << 16, hi = wd & 0xFFFF0000u;
    ull r; asm("mov.b64 %0,{%1,%2};" : "=l"(r) : "r"(lo), "r"(hi)); return r;
}
__device__ __forceinline__ float tanh_fast(float x) {
    float y; asm("tanh.approx.f32 %0, %1;" : "=f"(y) : "f"(x)); return y;
}
__device__ __forceinline__ float sigmoid_f(float x) {
    return 1.0f / (1.0f + __expf(-x));
}
__device__ __forceinline__ void fma4(float4& a, float s, const float4 w) {
    a.x = fmaf(s, w.x, a.x); a.y = fmaf(s, w.y, a.y);
    a.z = fmaf(s, w.z, a.z); a.w = fmaf(s, w.w, a.w);
}
__device__ __forceinline__ unsigned b2u(__nv_bfloat162 v) {
    unsigned r; *(__nv_bfloat162*)&r = v; return r;
}

// ---------------- kernel 0: weight layout prep --------------------------------
__global__ void prep_kernel(const float* __restrict__ W_attn1,
                            const float* __restrict__ W_ih,
                            const float* __restrict__ W_hh,
                            const float* __restrict__ b_ih,
                            const float* __restrict__ b_hh)
{
    int tid = blockIdx.x * blockDim.x + threadIdx.x;
    int nt  = gridDim.x * blockDim.x;
    // attention weights bf16: WhsB[j][kq] = {bf16x2(k0,k1), bf16x2(k2,k3)},
    // where W^T[j][k] = W_attn1[k*384 + j]  (j<128: W1_h col; j>=128: W1_s col)
    for (int i = tid; i < 256 * 32; i += nt) {
        int j = i >> 5, kq = i & 31, k = kq * 4;
        uint2 v;
        v.x = b2u(__floats2bfloat162_rn(W_attn1[(k+0)*384 + j], W_attn1[(k+1)*384 + j]));
        v.y = b2u(__floats2bfloat162_rn(W_attn1[(k+2)*384 + j], W_attn1[(k+3)*384 + j]));
        g_WhsB[i] = v;
    }
    for (int i = tid; i < TT * HH; i += nt) {
        int t = i >> 7, k = i & 127;
        g_W1xT[i] = W_attn1[k * 384 + 256 + t];
    }
    for (int i = tid; i < NN * 512; i += nt) {
        int n = i >> 9, r = i & 511, q = r >> 2, g = r & 3;
        g_WihG[i] = W_ih[(g * HH + q) * NN + n];
    }
    for (int i = tid; i < HH * 512; i += nt) {
        int j = i >> 9, r = i & 511, q = r >> 2, g = r & 3;
        g_WhhG[i] = W_hh[(g * HH + q) * HH + j];
    }
    for (int i = tid; i < 512; i += nt) {
        int q = i >> 2, g = i & 3;
        g_bG[i] = b_ih[g * HH + q] + b_hh[g * HH + q];
    }
}

// ---------------- kernel 1: pre_x (bf16 out) ----------------------------------
__global__ __launch_bounds__(256) void prex_kernel(const float* __restrict__ X,
                                                   const float* __restrict__ b_attn1)
{
    __shared__ float sX[TT * NN];
    int b = blockIdx.x;
    int tid = threadIdx.x;
    const float* Xb = X + (size_t)b * TT * NN;
    for (int i = tid; i < TT * NN; i += 256) sX[i] = Xb[i];
    __syncthreads();

    const float4* W4  = (const float4*)g_W1xT;
    const float4* b14 = (const float4*)b_attn1;
    uint2* out2 = (uint2*)(g_prex_bf + (size_t)b * NN * HH);

    for (int qi = tid; qi < NN * 32; qi += 256) {
        int n = qi >> 5, kq = qi & 31;
        float4 acc = b14[kq];
        #pragma unroll 4
        for (int t = 0; t < TT; ++t) {
            float x = sX[t * NN + n];
            fma4(acc, x, W4[t * 32 + kq]);
        }
        uint2 st;
        st.x = b2u(__floats2bfloat162_rn(acc.x, acc.y));
        st.y = b2u(__floats2bfloat162_rn(acc.z, acc.w));
        out2[n * 32 + kq] = st;
    }
}

// dummy: shifts launch numbering so ncu (-s 5 -c 1) lands on rnn_kernel
__global__ void dummy_kernel() {}

// ---------------- kernel 2: the recurrence ------------------------------------
// smem (floats): sWb 16384 (bf16 attn wts) | hcA 2112 | hcB 2112 | sU 1056 | sXT 512
#define SMEM_FLOATS (16384 + 2112 + 2112 + 1056 + 512)

__global__ __launch_bounds__(THR, 2) void rnn_kernel(
    const float* __restrict__ X,
    const float* __restrict__ w_attn2,
    const float* __restrict__ b_attn2,
    float* __restrict__ out)
{
    extern __shared__ float smem[];
    uint2* sWb = (uint2*)smem;            // [256][32]
    float* hcA = smem + 16384;
    float* hcB = hcA + 2112;
    float* sU  = hcB + 2112;
    float* sXT = sU + 1056;

    int tid = threadIdx.x;
    int l = tid & 31;
    int w = tid >> 5;                      // 0..7
    int cta = blockIdx.x;
    int cnt  = (cta < NFULL) ? 7 : 6;
    size_t b0 = (cta < NFULL) ? (size_t)cta * 7
                              : (size_t)(NFULL * 7 + (cta - NFULL) * 6);

    {   // stage bf16 attention weights into smem (once)
        const uint4* src = (const uint4*)g_WhsB;
        uint4* dst = (uint4*)sWb;
        #pragma unroll 4
        for (int i = tid; i < 4096; i += THR) dst[i] = src[i];
    }
    for (int i = tid; i < 4224; i += THR) hcA[i] = 0.0f;   // zero both hc buffers
    for (int i = tid; i < 512; i += THR) sXT[i] = 0.0f;

    float b2 = b_attn2[0];

    // (a) mapping: warp w -> batch-group (w>>2: 4 batches), k-group (w&3: 32 k)
    int mA  = (w >> 2) * 4 + (l >> 3);     // 0..7
    int kqA = (w & 3) * 8 + (l & 7);       // k-quad 0..31

    // (d) mapping: q in 0..127, 2 groups of 4 batches
    int q = tid & 127, grp = tid >> 7, mb = grp * 4;
    float4 bgq = ((const float4*)g_bG)[q];
    ull bLo = pk2(bgq.x, bgq.y), bHi = pk2(bgq.z, bgq.w);

    const ulonglong2* Whh2 = (const ulonglong2*)g_WhhG;
    const ulonglong2* Wih2 = (const ulonglong2*)g_WihG;
    int mw = (w < cnt) ? w : 0;
    const uint2* prb = (const uint2*)g_prex_bf + (size_t)(b0 + mw) * 2048;

    __syncthreads();

    for (int t = 0; t < TT; ++t) {
        float* hc  = (t & 1) ? hcB : hcA;
        float* hcn = (t & 1) ? hcA : hcB;

        // ---- (a) u[m][k] = sum_j [h|c][m][j] * WhsT[j][k]  (bf16 smem wts)
        {
            const float4* hcm4 = (const float4*)(hc + mA * HCP);
            ull a0 = 0ull, a1 = 0ull;
            #pragma unroll 4
            for (int j4 = 0; j4 < 64; ++j4) {
                float4 hv = hcm4[j4];
                uint2 w0 = sWb[(j4 * 4 + 0) * 32 + kqA];
                uint2 w1 = sWb[(j4 * 4 + 1) * 32 + kqA];
                uint2 w2 = sWb[(j4 * 4 + 2) * 32 + kqA];
                uint2 w3 = sWb[(j4 * 4 + 3) * 32 + kqA];
                ull p0 = pk2(hv.x, hv.x), p1 = pk2(hv.y, hv.y);
                ull p2 = pk2(hv.z, hv.z), p3 = pk2(hv.w, hv.w);
                fma2(a0, p0, expw(w0.x)); fma2(a1, p0, expw(w0.y));
                fma2(a0, p1, expw(w1.x)); fma2(a1, p1, expw(w1.y));
                fma2(a0, p2, expw(w2.x)); fma2(a1, p2, expw(w2.y));
                fma2(a0, p3, expw(w3.x)); fma2(a1, p3, expw(w3.y));
            }
            float2 r0 = up2(a0), r1 = up2(a1);
            ((float4*)(sU + mA * SUP))[kqA] = make_float4(r0.x, r0.y, r1.x, r1.y);
        }
        __syncthreads();

        // ---- (b)+(c): e, softmax, x_tilde. warp=m; lane ends with e[n=l].
        if (w < cnt) {
            int kq = l & 7;
            const float4* sUr = (const float4*)(sU + w * SUP);
            float4 u0 = sUr[kq], u1 = sUr[kq + 8], u2 = sUr[kq + 16], u3 = sUr[kq + 24];
            const float4* w24 = (const float4*)w_attn2;
            float4 wA = w24[kq], wB = w24[kq + 8], wC = w24[kq + 16], wD = w24[kq + 24];
            float ee[2];
            #pragma unroll
            for (int p = 0; p < 2; ++p) {
                int nb = p * 32 + (l & 24);
                const uint2* pp = prb + (size_t)nb * 32 + kq;
                uint2 c0 = __ldcs(pp), c1 = __ldcs(pp + 8);
                uint2 c2 = __ldcs(pp + 16), c3 = __ldcs(pp + 24);
                float v[8];
                #pragma unroll
                for (int i = 0; i < 8; ++i) {
                    const uint2* pn = prb + (size_t)(nb + ((i + 1) & 7)) * 32 + kq;
                    uint2 n0 = __ldcs(pn), n1 = __ldcs(pn + 8);
                    uint2 n2 = __ldcs(pn + 16), n3 = __ldcs(pn + 24);
                    float s;
                    {
                        float2 a01 = __bfloat1622float2(*(const __nv_bfloat162*)&c0.x);
                        float2 a23 = __bfloat1622float2(*(const __nv_bfloat162*)&c0.y);
                        s = tanh_fast(a01.x + u0.x) * wA.x;
                        s = fmaf(tanh_fast(a01.y + u0.y), wA.y, s);
                        s = fmaf(tanh_fast(a23.x + u0.z), wA.z, s);
                        s = fmaf(tanh_fast(a23.y + u0.w), wA.w, s);
                    }
                    {
                        float2 a01 = __bfloat1622float2(*(const __nv_bfloat162*)&c1.x);
                        float2 a23 = __bfloat1622float2(*(const __nv_bfloat162*)&c1.y);
                        s = fmaf(tanh_fast(a01.x + u1.x), wB.x, s);
                        s = fmaf(tanh_fast(a01.y + u1.y), wB.y, s);
                        s = fmaf(tanh_fast(a23.x + u1.z), wB.z, s);
                        s = fmaf(tanh_fast(a23.y + u1.w), wB.w, s);
                    }
                    {
                        float2 a01 = __bfloat1622float2(*(const __nv_bfloat162*)&c2.x);
                        float2 a23 = __bfloat1622float2(*(const __nv_bfloat162*)&c2.y);
                        s = fmaf(tanh_fast(a01.x + u2.x), wC.x, s);
                        s = fmaf(tanh_fast(a01.y + u2.y), wC.y, s);
                        s = fmaf(tanh_fast(a23.x + u2.z), wC.z, s);
                        s = fmaf(tanh_fast(a23.y + u2.w), wC.w, s);
                    }
                    {
                        float2 a01 = __bfloat1622float2(*(const __nv_bfloat162*)&c3.x);
                        float2 a23 = __bfloat1622float2(*(const __nv_bfloat162*)&c3.y);
                        s = fmaf(tanh_fast(a01.x + u3.x), wD.x, s);
                        s = fmaf(tanh_fast(a01.y + u3.y), wD.y, s);
                        s = fmaf(tanh_fast(a23.x + u3.z), wD.z, s);
                        s = fmaf(tanh_fast(a23.y + u3.w), wD.w, s);
                    }
                    v[i] = s;
                    c0 = n0; c1 = n1; c2 = n2; c3 = n3;
                }
                bool h1 = l & 1, h2 = l & 2, h4 = l & 4;
                float s0 = h1 ? v[0] : v[1];
                float a0 = (h1 ? v[1] : v[0]) + __shfl_xor_sync(0xffffffffu, s0, 1);
                float s1 = h1 ? v[2] : v[3];
                float a1 = (h1 ? v[3] : v[2]) + __shfl_xor_sync(0xffffffffu, s1, 1);
                float s2 = h1 ? v[4] : v[5];
                float a2 = (h1 ? v[5] : v[4]) + __shfl_xor_sync(0xffffffffu, s2, 1);
                float s3 = h1 ? v[6] : v[7];
                float a3 = (h1 ? v[7] : v[6]) + __shfl_xor_sync(0xffffffffu, s3, 1);
                float t0 = h2 ? a0 : a1;
                float bb0 = (h2 ? a1 : a0) + __shfl_xor_sync(0xffffffffu, t0, 2);
                float t1 = h2 ? a2 : a3;
                float bb1 = (h2 ? a3 : a2) + __shfl_xor_sync(0xffffffffu, t1, 2);
                float t2 = h4 ? bb0 : bb1;
                float ev = (h4 ? bb1 : bb0) + __shfl_xor_sync(0xffffffffu, t2, 4);
                ee[p] = ev + b2;
            }
            float e0 = ee[0], e1 = ee[1];
            float mx = fmaxf(e0, e1);
            #pragma unroll
            for (int o = 16; o > 0; o >>= 1)
                mx = fmaxf(mx, __shfl_xor_sync(0xffffffffu, mx, o));
            float x0 = __expf(e0 - mx), x1 = __expf(e1 - mx);
            float sm = x0 + x1;
            #pragma unroll
            for (int o = 16; o > 0; o >>= 1)
                sm += __shfl_xor_sync(0xffffffffu, sm, o);
            float inv = 1.0f / sm;
            const float* Xr = X + ((size_t)(b0 + w) * TT + t) * NN;
            sXT[w * 64 + l]      = x0 * inv * Xr[l];
            sXT[w * 64 + l + 32] = x1 * inv * Xr[l + 32];
        }
        __syncthreads();

        // ---- (d) gates for batches mb..mb+3 at gate-quad q (fp32 wts, prefetch)
        ull aL0 = bLo, aH0 = bHi, aL1 = bLo, aH1 = bHi;
        ull aL2 = bLo, aH2 = bHi, aL3 = bLo, aH3 = bHi;
        {
            const float4* h40 = (const float4*)(hc + (mb + 0) * HCP);
            const float4* h41 = (const float4*)(hc + (mb + 1) * HCP);
            const float4* h42 = (const float4*)(hc + (mb + 2) * HCP);
            const float4* h43 = (const float4*)(hc + (mb + 3) * HCP);
            const ulonglong2* Wh = Whh2 + q;
            ulonglong2 wq0 = Wh[0], wq1 = Wh[128], wq2 = Wh[256], wq3 = Wh[384];
            #pragma unroll 4
            for (int j4 = 0; j4 < 32; ++j4) {
                int nj = ((j4 + 1) & 31) * 4;
                ulonglong2 f0 = Wh[(size_t)(nj + 0) * 128];
                ulonglong2 f1 = Wh[(size_t)(nj + 1) * 128];
                ulonglong2 f2 = Wh[(size_t)(nj + 2) * 128];
                ulonglong2 f3 = Wh[(size_t)(nj + 3) * 128];
                float4 v0 = h40[j4], v1 = h41[j4], v2 = h42[j4], v3 = h43[j4];
                ull p0, p1, p2, p3;
                p0 = pk2(v0.x, v0.x); p1 = pk2(v1.x, v1.x); p2 = pk2(v2.x, v2.x); p3 = pk2(v3.x, v3.x);
                fma2(aL0, p0, wq0.x); fma2(aH0, p0, wq0.y);
                fma2(aL1, p1, wq0.x); fma2(aH1, p1, wq0.y);
                fma2(aL2, p2, wq0.x); fma2(aH2, p2, wq0.y);
                fma2(aL3, p3, wq0.x); fma2(aH3, p3, wq0.y);
                p0 = pk2(v0.y, v0.y); p1 = pk2(v1.y, v1.y); p2 = pk2(v2.y, v2.y); p3 = pk2(v3.y, v3.y);
                fma2(aL0, p0, wq1.x); fma2(aH0, p0, wq1.y);
                fma2(aL1, p1, wq1.x); fma2(aH1, p1, wq1.y);
                fma2(aL2, p2, wq1.x); fma2(aH2, p2, wq1.y);
                fma2(aL3, p3, wq1.x); fma2(aH3, p3, wq1.y);
                p0 = pk2(v0.z, v0.z); p1 = pk2(v1.z, v1.z); p2 = pk2(v2.z, v2.z); p3 = pk2(v3.z, v3.z);
                fma2(aL0, p0, wq2.x); fma2(aH0, p0, wq2.y);
                fma2(aL1, p1, wq2.x); fma2(aH1, p1, wq2.y);
                fma2(aL2, p2, wq2.x); fma2(aH2, p2, wq2.y);
                fma2(aL3, p3, wq2.x); fma2(aH3, p3, wq2.y);
                p0 = pk2(v0.w, v0.w); p1 = pk2(v1.w, v1.w); p2 = pk2(v2.w, v2.w); p3 = pk2(v3.w, v3.w);
                fma2(aL0, p0, wq3.x); fma2(aH0, p0, wq3.y);
                fma2(aL1, p1, wq3.x); fma2(aH1, p1, wq3.y);
                fma2(aL2, p2, wq3.x); fma2(aH2, p2, wq3.y);
                fma2(aL3, p3, wq3.x); fma2(aH3, p3, wq3.y);
                wq0 = f0; wq1 = f1; wq2 = f2; wq3 = f3;
            }
            const float4* x40 = (const float4*)(sXT + (mb + 0) * 64);
            const float4* x41 = (const float4*)(sXT + (mb + 1) * 64);
            const float4* x42 = (const float4*)(sXT + (mb + 2) * 64);
            const float4* x43 = (const float4*)(sXT + (mb + 3) * 64);
            const ulonglong2* Wi = Wih2 + q;
            wq0 = Wi[0]; wq1 = Wi[128]; wq2 = Wi[256]; wq3 = Wi[384];
            #pragma unroll 4
            for (int n4 = 0; n4 < 16; ++n4) {
                int nj = ((n4 + 1) & 15) * 4;
                ulonglong2 f0 = Wi[(size_t)(nj + 0) * 128];
                ulonglong2 f1 = Wi[(size_t)(nj + 1) * 128];
                ulonglong2 f2 = Wi[(size_t)(nj + 2) * 128];
                ulonglong2 f3 = Wi[(size_t)(nj + 3) * 128];
                float4 v0 = x40[n4], v1 = x41[n4], v2 = x42[n4], v3 = x43[n4];
                ull p0, p1, p2, p3;
                p0 = pk2(v0.x, v0.x); p1 = pk2(v1.x, v1.x); p2 = pk2(v2.x, v2.x); p3 = pk2(v3.x, v3.x);
                fma2(aL0, p0, wq0.x); fma2(aH0, p0, wq0.y);
                fma2(aL1, p1, wq0.x); fma2(aH1, p1, wq0.y);
                fma2(aL2, p2, wq0.x); fma2(aH2, p2, wq0.y);
                fma2(aL3, p3, wq0.x); fma2(aH3, p3, wq0.y);
                p0 = pk2(v0.y, v0.y); p1 = pk2(v1.y, v1.y); p2 = pk2(v2.y, v2.y); p3 = pk2(v3.y, v3.y);
                fma2(aL0, p0, wq1.x); fma2(aH0, p0, wq1.y);
                fma2(aL1, p1, wq1.x); fma2(aH1, p1, wq1.y);
                fma2(aL2, p2, wq1.x); fma2(aH2, p2, wq1.y);
                fma2(aL3, p3, wq1.x); fma2(aH3, p3, wq1.y);
                p0 = pk2(v0.z, v0.z); p1 = pk2(v1.z, v1.z); p2 = pk2(v2.z, v2.z); p3 = pk2(v3.z, v3.z);
                fma2(aL0, p0, wq2.x); fma2(aH0, p0, wq2.y);
                fma2(aL1, p1, wq2.x); fma2(aH1, p1, wq2.y);
                fma2(aL2, p2, wq2.x); fma2(aH2, p2, wq2.y);
                fma2(aL3, p3, wq2.x); fma2(aH3, p3, wq2.y);
                p0 = pk2(v0.w, v0.w); p1 = pk2(v1.w, v1.w); p2 = pk2(v2.w, v2.w); p3 = pk2(v3.w, v3.w);
                fma2(aL0, p0, wq3.x); fma2(aH0, p0, wq3.y);
                fma2(aL1, p1, wq3.x); fma2(aH1, p1, wq3.y);
                fma2(aL2, p2, wq3.x); fma2(aH2, p2, wq3.y);
                fma2(aL3, p3, wq3.x); fma2(aH3, p3, wq3.y);
                wq0 = f0; wq1 = f1; wq2 = f2; wq3 = f3;
            }
        }

        // ---- (e) LSTM pointwise update -> double-buffered state + output
        #pragma unroll
        for (int mm = 0; mm < 4; ++mm) {
            if (mb + mm < cnt) {
                ull aL = (mm == 0) ? aL0 : (mm == 1) ? aL1 : (mm == 2) ? aL2 : aL3;
                ull aH = (mm == 0) ? aH0 : (mm == 1) ? aH1 : (mm == 2) ? aH2 : aH3;
                float2 gif = up2(aL);
                float2 ggo = up2(aH);
                float iv = sigmoid_f(gif.x);
                float fv = sigmoid_f(gif.y);
                float gv = tanhf(ggo.x);
                float ov = sigmoid_f(ggo.y);
                float cold = hc[(mb + mm) * HCP + 128 + q];
                float c2 = fv * cold + iv * gv;
                float hn = ov * tanhf(c2);
                hcn[(mb + mm) * HCP + q]       = hn;
                hcn[(mb + mm) * HCP + 128 + q] = c2;
                out[((size_t)(b0 + mb + mm) * TT + t) * HH + q] = hn;
            }
        }
        __syncthreads();
    }
}

// ---------------- launch ------------------------------------------------------
extern "C" void kernel_launch(void* const* d_in, const int* in_sizes, int n_in,
                              void* d_out, int out_size) {
    const float* X       = (const float*)d_in[0];
    const float* W_attn1 = (const float*)d_in[1];
    const float* b_attn1 = (const float*)d_in[2];
    const float* w_attn2 = (const float*)d_in[3];
    const float* b_attn2 = (const float*)d_in[4];
    const float* W_ih    = (const float*)d_in[5];
    const float* W_hh    = (const float*)d_in[6];
    const float* b_ih    = (const float*)d_in[7];
    const float* b_hh    = (const float*)d_in[8];
    float* out = (float*)d_out;

    cudaFuncSetAttribute(rnn_kernel, cudaFuncAttributeMaxDynamicSharedMemorySize,
                         SMEM_FLOATS * (int)sizeof(float));

    prep_kernel<<<64, 256>>>(W_attn1, W_ih, W_hh, b_ih, b_hh);
    prex_kernel<<<BB, 256>>>(X, b_attn1);
    dummy_kernel<<<1, 32>>>();   // aligns ncu -s 5 -c 1 onto rnn_kernel
    rnn_kernel<<<GRID, THR, SMEM_FLOATS * sizeof(float)>>>(X, w_attn2, b_attn2, out);
}